// round 15
// baseline (speedup 1.0000x reference)
#include <cuda_runtime.h>
#include <cstdint>

// B=32, N=64, D=512
// score[b,i,j] = (dot(s_e[b,i,j,:], W) + bias) * adj[b,i,j], adj[b,0,1]=adj[b,1,0]=0
// Only i in {0,1} consumed. adj is 0/1: first half of each row is loaded
// speculatively (overlapped with the adj load); only the second half is gated.
// Outputs (float32, flattened tuple order):
//   final_id (32,2)=64 | s_e_score (32,2,64)=4096 | flag (32)=32

#define NB 32
#define NN 64
#define ND 512
#define GRID 64     // one block per output row (b*2+i)
#define TPB  1024   // 32 warps x 2 dots = the row's 64 dot products

__device__ int g_pair[NB] = {};   // per-batch arrival counter (reset by consumer)
__device__ int g_ids[NB * 2];     // int mirror of final_id (overwritten each launch)

__global__ void __launch_bounds__(TPB, 1)
fused_kernel(const float* __restrict__ s_e,
             const float* __restrict__ adj,
             const float* __restrict__ W,
             const float* __restrict__ bias,
             float* __restrict__ out_id,
             float* __restrict__ out_score,
             float* __restrict__ out_flag) {
    int warp = threadIdx.x >> 5;
    int lane = threadIdx.x & 31;

    int row = blockIdx.x;            // 0..63 == b*2 + i
    int b   = row >> 1;
    int i   = row & 1;
    int j0  = warp * 2;              // this warp's two j's: j0, j0+1

    __shared__ float s_score[NN];

    const float4* base0 =
        (const float4*)(s_e + ((size_t)((b * NN + i) * NN + j0)) * ND);
    const float4* base1 = base0 + (ND / 4);      // j0+1 (contiguous)
    const float4* wv = (const float4*)W;

    // ---- ONE latency exposure: adj + W + bias + FIRST HALF of both rows ----
    float adj_mine = 0.f;
    if (lane < 2)
        adj_mine = adj[(b * NN + i) * NN + j0 + lane];
    float bias0 = __ldg(bias);
    float4 w0 = wv[lane];
    float4 w1 = wv[32 + lane];
    float4 w2 = wv[64 + lane];
    float4 w3 = wv[96 + lane];
    float4 a0 = base0[lane];          // speculative: elements 0..255 of row j0
    float4 a1 = base0[32 + lane];
    float4 c0 = base1[lane];          // speculative: elements 0..255 of row j0+1
    float4 c1 = base1[32 + lane];

    float adj0 = __shfl_sync(0xffffffffu, adj_mine, 0);
    float adj1 = __shfl_sync(0xffffffffu, adj_mine, 1);
    if (j0 == 0) {                    // forced zeros at (0,1)/(1,0)
        if (i == 0) adj1 = 0.f;       // j = 1
        else        adj0 = 0.f;       // j = 0
    }

    // First-half partial sums (harmless garbage if adj==0; result *adj==0).
    float s0 = a0.x * w0.x + a0.y * w0.y + a0.z * w0.z + a0.w * w0.w
             + a1.x * w1.x + a1.y * w1.y + a1.z * w1.z + a1.w * w1.w;
    float s1 = c0.x * w0.x + c0.y * w0.y + c0.z * w0.z + c0.w * w0.w
             + c1.x * w1.x + c1.y * w1.y + c1.z * w1.z + c1.w * w1.w;

    // ---- Second half, gated by adj (saves ~2MB of dead reads) ----
    if (adj0 != 0.f) {
        float4 a2 = base0[64 + lane];
        float4 a3 = base0[96 + lane];
        s0 += a2.x * w2.x + a2.y * w2.y + a2.z * w2.z + a2.w * w2.w
            + a3.x * w3.x + a3.y * w3.y + a3.z * w3.z + a3.w * w3.w;
    }
    if (adj1 != 0.f) {
        float4 c2 = base1[64 + lane];
        float4 c3 = base1[96 + lane];
        s1 += c2.x * w2.x + c2.y * w2.y + c2.z * w2.z + c2.w * w2.w
            + c3.x * w3.x + c3.y * w3.y + c3.z * w3.z + c3.w * w3.w;
    }

#pragma unroll
    for (int off = 16; off; off >>= 1) {
        s0 += __shfl_xor_sync(0xffffffffu, s0, off);
        s1 += __shfl_xor_sync(0xffffffffu, s1, off);
    }

    if (lane == 0) {
        float sc0 = (s0 + bias0) * adj0;   // adj==0 -> exact 0
        float sc1 = (s1 + bias0) * adj1;
        s_score[j0]     = sc0;             // smem first: unblock argmax warp
        s_score[j0 + 1] = sc1;
        *(float2*)(out_score + row * NN + j0) = make_float2(sc0, sc1);
    }
    __syncthreads();

    // ---------- warp 0: row argmax from SMEM ----------
    if (warp == 0) {
        float v0 = s_score[lane];
        float v1 = s_score[lane + 32];
        float v; int idx;
        if (v1 > v0) { v = v1; idx = lane + 32; }
        else         { v = v0; idx = lane; }
#pragma unroll
        for (int off = 16; off; off >>= 1) {
            float ov = __shfl_xor_sync(0xffffffffu, v, off);
            int   oi = __shfl_xor_sync(0xffffffffu, idx, off);
            if (ov > v || (ov == v && oi < idx)) { v = ov; idx = oi; }
        }
        if (lane == 0) {
            out_id[row] = (float)idx;
            g_ids[row]  = idx;
            __threadfence();                     // publish before pairing
            int prev = atomicAdd(&g_pair[b], 1);
            if (prev == 1) {                     // partner row already done
                __threadfence();                 // acquire partner's write
                int other = g_ids[row ^ 1];
                int sub = (i == 0) ? idx   : other;
                int obj = (i == 0) ? other : idx;
                float f = 0.f;
                if (sub > 0 && obj > 0)      f = 3.f;
                else if (sub > 0)            f = 1.f;
                else if (obj > 0)            f = 2.f;
                out_flag[b] = f;
                g_pair[b] = 0;                   // reset for next replay
            }
        }
    }
}

extern "C" void kernel_launch(void* const* d_in, const int* in_sizes, int n_in,
                              void* d_out, int out_size) {
    const float* s_e  = (const float*)d_in[0];
    const float* adj  = (const float*)d_in[1];
    const float* W    = (const float*)d_in[2];
    const float* bias = (const float*)d_in[3];

    float* out       = (float*)d_out;
    float* out_id    = out;             // 64
    float* out_score = out + 64;        // 4096
    float* out_flag  = out + 64 + 4096; // 32

    fused_kernel<<<GRID, TPB>>>(s_e, adj, W, bias, out_id, out_score, out_flag);
}

// round 17
// speedup vs baseline: 1.2977x; 1.2977x over previous
#include <cuda_runtime.h>
#include <cstdint>

// B=32, N=64, D=512
// score[b,i,j] = (dot(s_e[b,i,j,:], W) + bias) * adj[b,i,j], adj[b,0,1]=adj[b,1,0]=0
// Only i in {0,1} consumed. adj is 0/1 -> skip dead 2KB s_e row reads (adj==0).
// One block per batch: both argmaxes + flag resolved in-block (no global sync).
// Outputs (float32, flattened tuple order):
//   final_id (32,2)=64 | s_e_score (32,2,64)=4096 | flag (32)=32

#define NB 32
#define NN 64
#define ND 512
#define GRID NB     // one block per batch b
#define TPB  1024   // 32 warps x 4 dots = the batch's 128 dot products

__global__ void __launch_bounds__(TPB, 1)
fused_kernel(const float* __restrict__ s_e,
             const float* __restrict__ adj,
             const float* __restrict__ W,
             const float* __restrict__ bias,
             float* __restrict__ out_id,
             float* __restrict__ out_score,
             float* __restrict__ out_flag) {
    int tid  = threadIdx.x;
    int warp = tid >> 5;
    int lane = tid & 31;
    int b    = blockIdx.x;

    __shared__ float s_adj[128];     // adj[b, 0:2, 0:64] with forced zeros
    __shared__ float s_score[128];   // scores for rows i=0, i=1
    __shared__ int   s_ids[2];

    // ---- Stage the batch's 128 adj values (one coalesced 512B load) ----
    if (tid < 128) {
        float a = adj[(size_t)b * (NN * NN) + tid];   // (i*64+j), i<2 contiguous
        if (tid == 1 || tid == 64) a = 0.f;           // (0,1) and (1,0) forced zero
        s_adj[tid] = a;
    }
    // W + bias load overlaps the adj staging.
    const float4* wv = (const float4*)W;
    float4 w0 = wv[lane];
    float4 w1 = wv[32 + lane];
    float4 w2 = wv[64 + lane];
    float4 w3 = wv[96 + lane];
    float bias0 = __ldg(bias);
    __syncthreads();

    // ---- Each warp: 4 consecutive dots p = warp*4 .. warp*4+3 (p = i*64+j) ----
    int pbase = warp * 4;
    const float* se_b = s_e + (size_t)b * (NN * NN * ND);  // rows i<2 contiguous
    float adj0 = s_adj[pbase];
    float adj1 = s_adj[pbase + 1];
    float adj2 = s_adj[pbase + 2];
    float adj3 = s_adj[pbase + 3];
    float sum0 = 0.f, sum1 = 0.f, sum2 = 0.f, sum3 = 0.f;

    {
        const float4* q0 = (const float4*)(se_b + (size_t)pbase * ND);
        const float4* q1 = q0 + (ND / 4);
        if (adj0 != 0.f) {
            float4 a0 = q0[lane], a1 = q0[32 + lane],
                   a2 = q0[64 + lane], a3 = q0[96 + lane];
            sum0 = a0.x * w0.x + a0.y * w0.y + a0.z * w0.z + a0.w * w0.w
                 + a1.x * w1.x + a1.y * w1.y + a1.z * w1.z + a1.w * w1.w
                 + a2.x * w2.x + a2.y * w2.y + a2.z * w2.z + a2.w * w2.w
                 + a3.x * w3.x + a3.y * w3.y + a3.z * w3.z + a3.w * w3.w;
        }
        if (adj1 != 0.f) {
            float4 c0 = q1[lane], c1 = q1[32 + lane],
                   c2 = q1[64 + lane], c3 = q1[96 + lane];
            sum1 = c0.x * w0.x + c0.y * w0.y + c0.z * w0.z + c0.w * w0.w
                 + c1.x * w1.x + c1.y * w1.y + c1.z * w1.z + c1.w * w1.w
                 + c2.x * w2.x + c2.y * w2.y + c2.z * w2.z + c2.w * w2.w
                 + c3.x * w3.x + c3.y * w3.y + c3.z * w3.z + c3.w * w3.w;
        }
    }
    {
        const float4* q2 = (const float4*)(se_b + (size_t)(pbase + 2) * ND);
        const float4* q3 = q2 + (ND / 4);
        if (adj2 != 0.f) {
            float4 a0 = q2[lane], a1 = q2[32 + lane],
                   a2 = q2[64 + lane], a3 = q2[96 + lane];
            sum2 = a0.x * w0.x + a0.y * w0.y + a0.z * w0.z + a0.w * w0.w
                 + a1.x * w1.x + a1.y * w1.y + a1.z * w1.z + a1.w * w1.w
                 + a2.x * w2.x + a2.y * w2.y + a2.z * w2.z + a2.w * w2.w
                 + a3.x * w3.x + a3.y * w3.y + a3.z * w3.z + a3.w * w3.w;
        }
        if (adj3 != 0.f) {
            float4 c0 = q3[lane], c1 = q3[32 + lane],
                   c2 = q3[64 + lane], c3 = q3[96 + lane];
            sum3 = c0.x * w0.x + c0.y * w0.y + c0.z * w0.z + c0.w * w0.w
                 + c1.x * w1.x + c1.y * w1.y + c1.z * w1.z + c1.w * w1.w
                 + c2.x * w2.x + c2.y * w2.y + c2.z * w2.z + c2.w * w2.w
                 + c3.x * w3.x + c3.y * w3.y + c3.z * w3.z + c3.w * w3.w;
        }
    }

    // 4 interleaved butterflies: ALL lanes participate (full mask is valid),
    // and after this every lane holds the complete sums.
#pragma unroll
    for (int off = 16; off; off >>= 1) {
        sum0 += __shfl_xor_sync(0xffffffffu, sum0, off);
        sum1 += __shfl_xor_sync(0xffffffffu, sum1, off);
        sum2 += __shfl_xor_sync(0xffffffffu, sum2, off);
        sum3 += __shfl_xor_sync(0xffffffffu, sum3, off);
    }

    // Lanes 0..3 each store one score; static selection, no collectives here.
    if (lane < 4) {
        float s = sum0, a = adj0;
        if (lane == 1) { s = sum1; a = adj1; }
        if (lane == 2) { s = sum2; a = adj2; }
        if (lane == 3) { s = sum3; a = adj3; }
        float scr = (s + bias0) * a;               // adj==0 -> exact 0
        s_score[pbase + lane] = scr;
        out_score[(size_t)b * 128 + pbase + lane] = scr;
    }
    __syncthreads();

    // ---- Warps 0/1: argmax over rows i=0/1 from smem ----
    if (warp < 2) {
        const float* rp = s_score + warp * NN;
        float v0 = rp[lane];
        float v1 = rp[lane + 32];
        float v; int idx;
        if (v1 > v0) { v = v1; idx = lane + 32; }
        else         { v = v0; idx = lane; }
#pragma unroll
        for (int off = 16; off; off >>= 1) {
            float ov = __shfl_xor_sync(0xffffffffu, v, off);
            int   oi = __shfl_xor_sync(0xffffffffu, idx, off);
            if (ov > v || (ov == v && oi < idx)) { v = ov; idx = oi; }
        }
        if (lane == 0) {
            s_ids[warp] = idx;
            out_id[b * 2 + warp] = (float)idx;
        }
    }
    __syncthreads();

    if (tid == 0) {
        int sub = s_ids[0];
        int obj = s_ids[1];
        float f = 0.f;
        if (sub > 0 && obj > 0)      f = 3.f;
        else if (sub > 0)            f = 1.f;
        else if (obj > 0)            f = 2.f;
        out_flag[b] = f;
    }
}

extern "C" void kernel_launch(void* const* d_in, const int* in_sizes, int n_in,
                              void* d_out, int out_size) {
    const float* s_e  = (const float*)d_in[0];
    const float* adj  = (const float*)d_in[1];
    const float* W    = (const float*)d_in[2];
    const float* bias = (const float*)d_in[3];

    float* out       = (float*)d_out;
    float* out_id    = out;             // 64
    float* out_score = out + 64;        // 4096
    float* out_flag  = out + 64 + 4096; // 32

    fused_kernel<<<GRID, TPB>>>(s_e, adj, W, bias, out_id, out_score, out_flag);
}